// round 15
// baseline (speedup 1.0000x reference)
#include <cuda_runtime.h>
#include <cstdint>

// DataWindowLoss: mean(|box5(x) - box5(y)|), padding=4, x/y: [64,1,512,512] fp32.
// box(x)-box(y) = box(x-y); separable 5x5 box; |c*s| = c*|s|.
// cp.async 3-stage smem pipeline (raw x,y; 2 chunks in flight -> flat DRAM
// demand), 3-row chunks, 129 owner threads x 4 cols with shfl halo, P-carry
// vertical box, one balanced wave of 296 blocks, fused finalize.

#define BATCH   64
#define H       512
#define W       512
#define OW      516
#define OH      516
#define G_ROWS  (BATCH * OH)        // 33024
#define NB      296                 // 2 blocks/SM * 148 SMs: one balanced wave
#define BLOCK   384                 // 12 warps; 3 rows * 128 float4-slots
#define NWARPS  (BLOCK / 32)
#define CR      3                   // rows per chunk
#define S       3                   // pipeline stages (2 chunks in flight)
#define ROWLEN  520                 // 4 zero-pad + 512 + 4 zero-pad
#define NOWN    129                 // owner threads, 4 output cols each (516)

__device__ double   g_acc;
__device__ unsigned g_count;

__device__ __forceinline__ void cp16(uint32_t dst, const float* src) {
    asm volatile("cp.async.cg.shared.global [%0], [%1], 16;" :: "r"(dst), "l"(src));
}
__device__ __forceinline__ void cp_commit() {
    asm volatile("cp.async.commit_group;");
}
__device__ __forceinline__ void cp_wait1() {
    asm volatile("cp.async.wait_group 1;");
}

__global__ __launch_bounds__(BLOCK, 2)
void box_loss_kernel(const float* __restrict__ x, const float* __restrict__ y,
                     float* __restrict__ out) {
    __shared__ float sx[S][CR][ROWLEN];     // 18.7 KB raw x rows
    __shared__ float sy[S][CR][ROWLEN];     // 18.7 KB raw y rows
    __shared__ float wsum[NWARPS];

    const int tid  = threadIdx.x;
    const int lrow = tid >> 7;              // 0..2 : chunk row this thread fills
    const int lcol = (tid & 127) << 2;      // 0..508 : float4 column

    // Zero the pads once (never rewritten): 2 arrays * 9 rows * 2 sides.
    if (tid < 2 * S * CR * 2) {
        const int arr  = tid / (S * CR * 2);
        const int rem  = tid % (S * CR * 2);
        const int rrow = rem >> 1, side = rem & 1;
        float* rp = arr ? &sy[rrow / CR][rrow % CR][0] : &sx[rrow / CR][rrow % CR][0];
        float4 z = make_float4(0.f, 0.f, 0.f, 0.f);
        *(float4*)(rp + (side ? 516 : 0)) = z;
    }

    float acc = 0.f;

    const int g0 = (int)((long long)blockIdx.x       * G_ROWS / NB);
    const int g1 = (int)((long long)(blockIdx.x + 1) * G_ROWS / NB);

    // Owner mapping: warps 0..4 (160 threads) run the consume uniformly;
    // threads >= NOWN shadow owner 128 and are masked at accumulation.
    const int  ot     = (tid < NOWN) ? tid : (NOWN - 1);
    const bool is_own = (tid < NOWN);
    const bool lane0  = ((tid & 31) == 0);

    int g = g0;
    while (g < g1) {                         // per-batch segment (<=2 per block)
        const int b  = g / OH;
        const int s0 = g - b * OH;
        int n = g1 - g;
        if (n > OH - s0) n = OH - s0;
        const int steps  = n + 4;
        const int nchunk = (steps + CR - 1) / CR;
        const int vrb    = s0 - 4;
        const float* xr = x + (size_t)b * (H * W) + lcol;
        const float* yr = y + (size_t)b * (H * W) + lcol;

        __syncthreads();                     // smem reuse fence (segment start)

        // Issue one chunk's worth of cp.async (or zeros) for chunk cc.
        #define ISSUE(CC) do {                                                 \
            const int _c = (CC);                                               \
            if (_c < nchunk) {                                                 \
                const int _stg = _c % S;                                       \
                const int _st  = _c * CR + lrow;                               \
                const int _gr  = vrb + _st;                                    \
                float* _px = &sx[_stg][lrow][4 + lcol];                        \
                float* _py = &sy[_stg][lrow][4 + lcol];                        \
                if (_st < steps && (unsigned)_gr < (unsigned)H) {              \
                    cp16((uint32_t)__cvta_generic_to_shared(_px),              \
                         xr + (size_t)_gr * W);                                \
                    cp16((uint32_t)__cvta_generic_to_shared(_py),              \
                         yr + (size_t)_gr * W);                                \
                } else {                                                       \
                    float4 _z = make_float4(0.f, 0.f, 0.f, 0.f);               \
                    *(float4*)_px = _z;                                        \
                    *(float4*)_py = _z;                                        \
                }                                                              \
            }                                                                  \
            cp_commit();                                                       \
        } while (0)

        // Prologue: chunks 0 and 1 in flight.
        ISSUE(0);
        ISSUE(1);

        // Vertical history: P1..P5 = h of rows t-1..t-5 (per owned col).
        float P1a=0.f,P2a=0.f,P3a=0.f,P4a=0.f,P5a=0.f;
        float P1b=0.f,P2b=0.f,P3b=0.f,P4b=0.f,P5b=0.f;
        float P1c=0.f,P2c=0.f,P3c=0.f,P4c=0.f,P5c=0.f;
        float P1d=0.f,P2d=0.f,P3d=0.f,P4d=0.f,P5d=0.f;
        float v0=0.f, v1=0.f, v2=0.f, v3=0.f;

        #pragma unroll 1
        for (int c = 0; c < nchunk; ++c) {
            cp_wait1();                      // this thread's chunk c landed
            __syncthreads();                 // everyone's chunk c landed;
                                             // chunk c-1 fully consumed
            ISSUE(c + 2);                    // refill stage (c-1)%S

            const int stg = c % S;
            if (tid < 160) {                 // warps 0..4: uniform consume
                float h0s[CR-1][4];          // h of rows 0..1 (row2 -> P1)
                float hl0=0.f,hl1=0.f,hl2=0.f,hl3=0.f;
                #pragma unroll
                for (int rr = 0; rr < CR; ++rr) {
                    const float4 xv = *(const float4*)&sx[stg][rr][(ot << 2) + 4];
                    const float4 yv = *(const float4*)&sy[stg][rr][(ot << 2) + 4];
                    const float d0 = xv.x - yv.x, d1 = xv.y - yv.y;
                    const float d2 = xv.z - yv.z, d3 = xv.w - yv.w;
                    // halo: prev owner's diffs (shfl), warp-edge via smem
                    float p0 = __shfl_up_sync(0xffffffffu, d0, 1);
                    float p1 = __shfl_up_sync(0xffffffffu, d1, 1);
                    float p2 = __shfl_up_sync(0xffffffffu, d2, 1);
                    float p3 = __shfl_up_sync(0xffffffffu, d3, 1);
                    if (lane0) {
                        const float4 hx = *(const float4*)&sx[stg][rr][ot << 2];
                        const float4 hy = *(const float4*)&sy[stg][rr][ot << 2];
                        p0 = hx.x - hy.x; p1 = hx.y - hy.y;
                        p2 = hx.z - hy.z; p3 = hx.w - hy.w;
                    }
                    // horizontal 5-sums, incremental
                    const float h0 = ((p0 + p1) + (p2 + p3)) + d0;
                    const float h1 = h0 - p0 + d1;
                    const float h2 = h1 - p1 + d2;
                    const float h3 = h2 - p2 + d3;
                    // vertical incremental: v += h_new - h_{t-5}
                    if (rr == 0)      { v0 += h0 - P5a; v1 += h1 - P5b;
                                        v2 += h2 - P5c; v3 += h3 - P5d; }
                    else if (rr == 1) { v0 += h0 - P4a; v1 += h1 - P4b;
                                        v2 += h2 - P4c; v3 += h3 - P4d; }
                    else              { v0 += h0 - P3a; v1 += h1 - P3b;
                                        v2 += h2 - P3c; v3 += h3 - P3d; }
                    if (rr < CR - 1) {
                        h0s[rr][0] = h0; h0s[rr][1] = h1;
                        h0s[rr][2] = h2; h0s[rr][3] = h3;
                    } else { hl0 = h0; hl1 = h1; hl2 = h2; hl3 = h3; }
                    const int step = c * CR + rr;
                    if (is_own && step >= 4 && step < steps)
                        acc += (fabsf(v0) + fabsf(v1)) + (fabsf(v2) + fabsf(v3));
                }
                // shift history by CR=3: P5'=P2, P4'=P1, P3'=h(row0),
                // P2'=h(row1), P1'=h(row2)
                P5a=P2a; P4a=P1a; P3a=h0s[0][0]; P2a=h0s[1][0]; P1a=hl0;
                P5b=P2b; P4b=P1b; P3b=h0s[0][1]; P2b=h0s[1][1]; P1b=hl1;
                P5c=P2c; P4c=P1c; P3c=h0s[0][2]; P2c=h0s[1][2]; P1c=hl2;
                P5d=P2d; P4d=P1d; P3d=h0s[0][3]; P2d=h0s[1][3]; P1d=hl3;
            }
        }
        #undef ISSUE
        g += n;
    }

    // Block reduction -> one double atomic per block.
    #pragma unroll
    for (int off = 16; off; off >>= 1)
        acc += __shfl_xor_sync(0xffffffffu, acc, off);
    if ((tid & 31) == 0) wsum[tid >> 5] = acc;
    __syncthreads();
    if (tid == 0) {
        float t = 0.f;
        #pragma unroll
        for (int w = 0; w < NWARPS; ++w) t += wsum[w];
        atomicAdd(&g_acc, (double)t);
        __threadfence();
        const unsigned ticket = atomicAdd(&g_count, 1u);
        if (ticket == NB - 1) {              // last block finalizes + resets
            const double total = atomicAdd(&g_acc, 0.0);
            out[0] = (float)(total / 25.0 / ((double)BATCH * OH * OW));
            g_acc = 0.0;
            __threadfence();
            g_count = 0u;
        }
    }
}

extern "C" void kernel_launch(void* const* d_in, const int* in_sizes, int n_in,
                              void* d_out, int out_size) {
    (void)in_sizes; (void)n_in; (void)out_size;
    const float* x = (const float*)d_in[0];
    const float* y = (const float*)d_in[1];
    float* out = (float*)d_out;
    box_loss_kernel<<<NB, BLOCK>>>(x, y, out);
}

// round 17
// speedup vs baseline: 1.3730x; 1.3730x over previous
#include <cuda_runtime.h>

// DataWindowLoss: mean(|box5(x) - box5(y)|), padding=4, x/y: [64,1,512,512] fp32.
// box(x)-box(y) = box(x-y); separable 5x5 box; |c*s| = c*|s|.
// Small-block phase-diverse streaming: 256-thread blocks, 4 blocks/SM (592 =
// one balanced wave), 2-row chunks, 1-deep register staging, diff smem,
// 129 owners x 4 cols, P-carry vertical box, fused finalize.

#define BATCH   64
#define H       512
#define W       512
#define OW      516
#define OH      516
#define G_ROWS  (BATCH * OH)        // 33024
#define NB      592                 // 4 blocks/SM * 148 SMs: one balanced wave
#define BLOCK   256                 // 8 warps; 2 rows * 128 float4-loaders
#define NWARPS  (BLOCK / 32)
#define CR      2                   // rows per chunk
#define ROWLEN  520                 // 4 zero-pad + 512 + 4 zero-pad
#define NOWN    129                 // owner threads, 4 output cols each (516)

__device__ double   g_acc;
__device__ unsigned g_count;

__global__ __launch_bounds__(BLOCK, 4)
void box_loss_kernel(const float* __restrict__ x, const float* __restrict__ y,
                     float* __restrict__ out) {
    __shared__ float sbuf[2][CR][ROWLEN];   // 8.32 KB double-buffered diff rows
    __shared__ float wsum[NWARPS];

    const int tid  = threadIdx.x;
    const int lrow = tid >> 7;              // 0..1 : chunk row this thread loads
    const int lcol = (tid & 127) << 2;      // 0..508 : float4 column

    // Zero the pads once: 2 buffers * 2 rows * 2 sides = 8 float4 stores.
    if (tid < 8) {
        const int buf = tid >> 2, rr = (tid >> 1) & 1, side = tid & 1;
        *(float4*)&sbuf[buf][rr][side ? 516 : 0] = make_float4(0.f, 0.f, 0.f, 0.f);
    }

    float acc = 0.f;

    const int g0 = (int)((long long)blockIdx.x       * G_ROWS / NB);
    const int g1 = (int)((long long)(blockIdx.x + 1) * G_ROWS / NB);

    // Warps 0..4 (160 threads) run consume uniformly; threads >= NOWN shadow
    // owner 128 and are masked at accumulation (keeps branches warp-uniform).
    const int  ot     = (tid < NOWN) ? tid : (NOWN - 1);
    const bool is_own = (tid < NOWN);

    int g = g0;
    while (g < g1) {                         // per-batch segment (<=2 per block)
        const int b  = g / OH;
        const int s0 = g - b * OH;
        int n = g1 - g;
        if (n > OH - s0) n = OH - s0;
        const int steps  = n + 4;
        const int nchunk = (steps + CR - 1) / CR;
        const int vrb    = s0 - 4;
        const float* xr = x + (size_t)b * (H * W) + lcol;
        const float* yr = y + (size_t)b * (H * W) + lcol;

        __syncthreads();                     // smem reuse fence (segment start)

        // Stage chunk 0.
        float4 rx = make_float4(0.f, 0.f, 0.f, 0.f), ry = rx;
        {
            const int gr = vrb + lrow;
            if ((unsigned)gr < (unsigned)H) {
                rx = __ldcs((const float4*)(xr + (size_t)gr * W));
                ry = __ldcs((const float4*)(yr + (size_t)gr * W));
            }
        }

        // Vertical history: Pk = h of row (t-k), per owned col a..d.
        float P1a=0.f,P2a=0.f,P3a=0.f,P4a=0.f,P5a=0.f;
        float P1b=0.f,P2b=0.f,P3b=0.f,P4b=0.f,P5b=0.f;
        float P1c=0.f,P2c=0.f,P3c=0.f,P4c=0.f,P5c=0.f;
        float P1d=0.f,P2d=0.f,P3d=0.f,P4d=0.f,P5d=0.f;
        float v0=0.f, v1=0.f, v2=0.f, v3=0.f;

        #pragma unroll 1
        for (int c = 0; c < nchunk; ++c) {
            const int p = c & 1;

            // Commit staged diff to smem buffer p.
            {
                float4 d;
                d.x = rx.x - ry.x;  d.y = rx.y - ry.y;
                d.z = rx.z - ry.z;  d.w = rx.w - ry.w;
                *(float4*)&sbuf[p][lrow][4 + lcol] = d;
            }

            // Prefetch chunk c+1.
            rx = make_float4(0.f, 0.f, 0.f, 0.f); ry = rx;
            if (c + 1 < nchunk) {
                const int st = (c + 1) * CR + lrow;
                const int gr = vrb + st;
                if (st < steps && (unsigned)gr < (unsigned)H) {
                    rx = __ldcs((const float4*)(xr + (size_t)gr * W));
                    ry = __ldcs((const float4*)(yr + (size_t)gr * W));
                }
            }

            __syncthreads();                 // one barrier per chunk

            // Consume 2 rows: 4 output cols per owner, 2x LDS.128 per row.
            if (tid < 160) {
                float hr0a, hr0b, hr0c, hr0d;   // h of chunk row 0
                float hr1a, hr1b, hr1c, hr1d;   // h of chunk row 1
                {   // rr = 0
                    const float* q = &sbuf[p][0][ot << 2];
                    const float4 a  = *(const float4*)q;        // sd[4t..4t+3]
                    const float4 bq = *(const float4*)(q + 4);  // sd[4t+4..4t+7]
                    const float h0 = ((a.x + a.y) + (a.z + a.w)) + bq.x;
                    const float h1 = h0 - a.x + bq.y;
                    const float h2 = h1 - a.y + bq.z;
                    const float h3 = h2 - a.z + bq.w;
                    v0 += h0 - P5a;  v1 += h1 - P5b;
                    v2 += h2 - P5c;  v3 += h3 - P5d;
                    hr0a = h0; hr0b = h1; hr0c = h2; hr0d = h3;
                    const int step = c * CR;
                    if (is_own && step >= 4 && step < steps)
                        acc += (fabsf(v0) + fabsf(v1)) + (fabsf(v2) + fabsf(v3));
                }
                {   // rr = 1
                    const float* q = &sbuf[p][1][ot << 2];
                    const float4 a  = *(const float4*)q;
                    const float4 bq = *(const float4*)(q + 4);
                    const float h0 = ((a.x + a.y) + (a.z + a.w)) + bq.x;
                    const float h1 = h0 - a.x + bq.y;
                    const float h2 = h1 - a.y + bq.z;
                    const float h3 = h2 - a.z + bq.w;
                    v0 += h0 - P4a;  v1 += h1 - P4b;
                    v2 += h2 - P4c;  v3 += h3 - P4d;
                    hr1a = h0; hr1b = h1; hr1c = h2; hr1d = h3;
                    const int step = c * CR + 1;
                    if (is_own && step >= 4 && step < steps)
                        acc += (fabsf(v0) + fabsf(v1)) + (fabsf(v2) + fabsf(v3));
                }
                // Shift history by 2 rows.
                P5a=P3a; P4a=P2a; P3a=P1a; P2a=hr0a; P1a=hr1a;
                P5b=P3b; P4b=P2b; P3b=P1b; P2b=hr0b; P1b=hr1b;
                P5c=P3c; P4c=P2c; P3c=P1c; P2c=hr0c; P1c=hr1c;
                P5d=P3d; P4d=P2d; P3d=P1d; P2d=hr0d; P1d=hr1d;
            }
            // Double buffering: next STS targets the other buffer; reuse of
            // this one is fenced by the next chunk's barrier.
        }
        g += n;
    }

    // Block reduction -> one double atomic per block.
    #pragma unroll
    for (int off = 16; off; off >>= 1)
        acc += __shfl_xor_sync(0xffffffffu, acc, off);
    if ((tid & 31) == 0) wsum[tid >> 5] = acc;
    __syncthreads();
    if (tid == 0) {
        float t = 0.f;
        #pragma unroll
        for (int w = 0; w < NWARPS; ++w) t += wsum[w];
        atomicAdd(&g_acc, (double)t);
        __threadfence();
        const unsigned ticket = atomicAdd(&g_count, 1u);
        if (ticket == NB - 1) {              // last block finalizes + resets
            const double total = atomicAdd(&g_acc, 0.0);
            out[0] = (float)(total / 25.0 / ((double)BATCH * OH * OW));
            g_acc = 0.0;
            __threadfence();
            g_count = 0u;
        }
    }
}

extern "C" void kernel_launch(void* const* d_in, const int* in_sizes, int n_in,
                              void* d_out, int out_size) {
    (void)in_sizes; (void)n_in; (void)out_size;
    const float* x = (const float*)d_in[0];
    const float* y = (const float*)d_in[1];
    float* out = (float*)d_out;
    box_loss_kernel<<<NB, BLOCK>>>(x, y, out);
}